// round 1
// baseline (speedup 1.0000x reference)
#include <cuda_runtime.h>

// Problem constants: x is (8, 48, 48, 48, 64) fp32.
// K = reshape(x, (B, C, N)) with C=64, N=48*48*48=110592 — a raw reinterpret:
// row c of K is the contiguous chunk x[b, c*N : (c+1)*N].
#define CCH   64
#define NCOL  110592
#define BATCH 8
#define CN    (CCH * NCOL)          // 7,077,888 per batch

#define CHUNK  2048
#define NCHUNK (NCOL / CHUNK)        // 54
#define TK     16
#define TN     128                   // n-tile for the weights kernel

// Static device scratch (no runtime allocation allowed).
// Partial Gram matrices: one 64x64 per (batch, chunk) block — deterministic
// two-stage reduction instead of float atomics.
__device__ float g_part[BATCH * NCHUNK * CCH * CCH];  // ~7.08 MB
__device__ float g_aff [BATCH * CCH * CCH];           // sigmoid(G@G)

// ---------------------------------------------------------------------------
// Kernel 1: partial Gram G_part = K_chunk @ K_chunk^T  (64x64 per block)
// grid (NCHUNK, BATCH), 256 threads, thread computes a 4x4 output tile.
// ---------------------------------------------------------------------------
__global__ void gram_partial(const float* __restrict__ x) {
    __shared__ float Ks[TK][CCH + 4];   // +4 pad keeps rows 16B-aligned, avoids conflicts

    const int tid = threadIdx.x;
    const int tx  = tid & 15;           // 0..15 -> output cols tx*4..tx*4+3
    const int ty  = tid >> 4;           // 0..15 -> output rows ty*4..ty*4+3
    const int b   = blockIdx.y;
    const long n0 = (long)blockIdx.x * CHUNK;
    const float* Kb = x + (long)b * CN;

    // loader mapping: each thread loads one float4 of a 64x16 tile
    const int lc = tid >> 2;            // channel row 0..63
    const int lj = (tid & 3) * 4;       // col offset 0,4,8,12

    float acc[4][4] = {};

    for (int k0 = 0; k0 < CHUNK; k0 += TK) {
        float4 v = *(const float4*)(Kb + (long)lc * NCOL + n0 + k0 + lj);
        Ks[lj + 0][lc] = v.x;
        Ks[lj + 1][lc] = v.y;
        Ks[lj + 2][lc] = v.z;
        Ks[lj + 3][lc] = v.w;
        __syncthreads();

#pragma unroll
        for (int kk = 0; kk < TK; kk++) {
            float4 av = *(const float4*)&Ks[kk][ty * 4];
            float4 bv = *(const float4*)&Ks[kk][tx * 4];
            float ar[4] = {av.x, av.y, av.z, av.w};
            float br[4] = {bv.x, bv.y, bv.z, bv.w};
#pragma unroll
            for (int i = 0; i < 4; i++)
#pragma unroll
                for (int j = 0; j < 4; j++)
                    acc[i][j] = fmaf(ar[i], br[j], acc[i][j]);
        }
        __syncthreads();
    }

    float* outp = g_part + ((long)b * NCHUNK + blockIdx.x) * (CCH * CCH);
#pragma unroll
    for (int i = 0; i < 4; i++) {
        *(float4*)&outp[(ty * 4 + i) * CCH + tx * 4] =
            make_float4(acc[i][0], acc[i][1], acc[i][2], acc[i][3]);
    }
}

// ---------------------------------------------------------------------------
// Kernel 2: reduce partials -> G, then m3 = G@G (G symmetric), sigmoid.
// grid (BATCH), 256 threads. Tiny kernel.
// ---------------------------------------------------------------------------
__global__ void m3_sigmoid() {
    __shared__ float Gs[CCH * CCH];     // 16 KB

    const int b   = blockIdx.x;
    const int tid = threadIdx.x;

    // Deterministic reduction of 54 partials
    for (int idx = tid; idx < CCH * CCH; idx += 256) {
        const float* p = g_part + (long)b * NCHUNK * (CCH * CCH) + idx;
        float s = 0.0f;
#pragma unroll 6
        for (int ch = 0; ch < NCHUNK; ch++) s += p[ch * (CCH * CCH)];
        Gs[idx] = s;
    }
    __syncthreads();

    // m3[c][e] = sum_d G[c][d] * G[e][d]  (G symmetric), 16 outputs/thread
    const int c  = tid >> 2;            // 0..63
    const int e0 = (tid & 3) * 16;
    for (int e = e0; e < e0 + 16; e++) {
        float s = 0.0f;
#pragma unroll
        for (int d = 0; d < CCH; d++)
            s = fmaf(Gs[c * CCH + d], Gs[e * CCH + d], s);
        // sigmoid; values are enormous (~1e10) so saturation is expected & exact
        g_aff[b * (CCH * CCH) + c * CCH + e] = 1.0f / (1.0f + __expf(-s));
    }
}

// ---------------------------------------------------------------------------
// Kernel 3: out = x + gamma * (A @ K).  Output tile 64 x 128 per block.
// grid (NCOL/TN, BATCH), 256 threads, 4x8 register tile per thread.
// x[c,n] == Ks[c][n] (same flat layout), so the epilogue needs no extra read.
// ---------------------------------------------------------------------------
__global__ void weights_out(const float* __restrict__ x,
                            const float* __restrict__ gamma_p,
                            float* __restrict__ out) {
    __shared__ float As[CCH * CCH];     // affinity (symmetric), 16 KB
    __shared__ float Ks[CCH][TN];       // 32 KB  (total 48 KB exactly)

    const int tid = threadIdx.x;
    const int b   = blockIdx.y;
    const long n0 = (long)blockIdx.x * TN;
    const float* Kb = x + (long)b * CN;

    // Load affinity
    for (int idx = tid; idx < CCH * CCH; idx += 256)
        As[idx] = g_aff[b * (CCH * CCH) + idx];

    // Load K tile: 64 rows x 128 cols. 4 threads per row, 8 float4 each.
    {
        const int r = tid >> 2;         // row 0..63
        const int j = tid & 3;          // 0..3 -> cols j*32 .. j*32+31
#pragma unroll
        for (int i = 0; i < 8; i++) {
            float4 v = *(const float4*)(Kb + (long)r * NCOL + n0 + j * 32 + i * 4);
            *(float4*)&Ks[r][j * 32 + i * 4] = v;
        }
    }
    __syncthreads();

    const int tx = tid & 15;            // n-groups: cols tx*4..+3 and 64+tx*4..+3
    const int ty = tid >> 4;            // c rows ty*4..ty*4+3

    float acc[4][8] = {};

#pragma unroll 8
    for (int d = 0; d < CCH; d++) {
        float4 av = *(const float4*)&As[d * CCH + ty * 4];  // A[d][c..] == A[c..][d] (symmetric)
        float4 b0 = *(const float4*)&Ks[d][tx * 4];
        float4 b1 = *(const float4*)&Ks[d][64 + tx * 4];
        float ar[4] = {av.x, av.y, av.z, av.w};
        float br[8] = {b0.x, b0.y, b0.z, b0.w, b1.x, b1.y, b1.z, b1.w};
#pragma unroll
        for (int i = 0; i < 4; i++)
#pragma unroll
            for (int j = 0; j < 8; j++)
                acc[i][j] = fmaf(ar[i], br[j], acc[i][j]);
    }

    const float gamma = *gamma_p;

#pragma unroll
    for (int i = 0; i < 4; i++) {
        const int c = ty * 4 + i;
        float4 k0 = *(const float4*)&Ks[c][tx * 4];
        float4 k1 = *(const float4*)&Ks[c][64 + tx * 4];
        float4 o0 = make_float4(fmaf(gamma, acc[i][0], k0.x),
                                fmaf(gamma, acc[i][1], k0.y),
                                fmaf(gamma, acc[i][2], k0.z),
                                fmaf(gamma, acc[i][3], k0.w));
        float4 o1 = make_float4(fmaf(gamma, acc[i][4], k1.x),
                                fmaf(gamma, acc[i][5], k1.y),
                                fmaf(gamma, acc[i][6], k1.z),
                                fmaf(gamma, acc[i][7], k1.w));
        float* dst = out + (long)b * CN + (long)c * NCOL + n0;
        *(float4*)(dst + tx * 4)      = o0;
        *(float4*)(dst + 64 + tx * 4) = o1;
    }
}

// ---------------------------------------------------------------------------
extern "C" void kernel_launch(void* const* d_in, const int* in_sizes, int n_in,
                              void* d_out, int out_size) {
    const float* x     = (const float*)d_in[0];
    const float* gamma = (const float*)d_in[1];
    float*       out   = (float*)d_out;

    gram_partial<<<dim3(NCHUNK, BATCH), 256>>>(x);
    m3_sigmoid  <<<BATCH, 256>>>();
    weights_out <<<dim3(NCOL / TN, BATCH), 256>>>(x, gamma, out);
}